// round 10
// baseline (speedup 1.0000x reference)
#include <cuda_runtime.h>

// ---------------- problem constants ----------------
#define TDIM   2048
#define BDIM   16384
#define NTS    18431            // TDIM + BDIM - 1
#define MQ     24               // seasonality period == HORIZON
#define XOUT_N (BDIM * TDIM)    // 33554432
#define DEN_N  (BDIM * 48)      // 786432

// ---------------- chunk-parallel scan config (R7 layout) ----------------
#define W_UP   1440             // warm-up steps (60 seasonal cycles)
#define WMACRO (W_UP / MQ)      // 60
#define CH_S   19               // output steps per chunk
#define WPB    4                // warps (=chunks) per block
#define K3_BT  (WPB * 32)       // 128 threads
#define K3_NB  243              // 972 chunk slots >= 971 needed
#define NCHUNK 1024             // logical chunk-index space
#define BSPAN  (WPB * CH_S)     // 76 output steps per block
#define SLICE  (W_UP + BSPAN)   // 1516 ts floats used
#define TSBUF  2080             // sm_ts size: >= SLICE+32 pad, >= 2048 for prefix

#define XB     (XOUT_N / 4 / 256)        // 32768 xout blocks
#define DB     ((DEN_N + 255) / 256)     // 3072 denorm blocks

// ---------------- device scratch (no allocs allowed) ----------------
__device__ __align__(16) float g_xnsh[4][18448];   // 4 shifted copies of xn
__device__ float g_l [NTS];
__device__ float g_s [NTS];
__device__ float g_lstart[NCHUNK];
__device__ float g_lend  [NCHUNK];
__device__ float g_c     [NCHUNK];
__device__ unsigned g_cnt;                         // zero-init; reset each launch

__device__ __forceinline__ float frcp(float x) {
    float r;
    asm("rcp.approx.ftz.f32 %0, %1;" : "=f"(r) : "f"(x));
    return r;
}

// ============ K1: lane-per-slot warp-parallel ES scan (R7 numerics) ========
// One warp = one 19-step chunk warm-started 1440 steps back. Lane j owns
// seasonal slot j. Level chain solved per 24-step macro by a Kogge-Stone
// affine scan. Epilogue additionally writes the 4 shifted xn copies, and the
// LAST block to finish runs the 1024-entry prefix product (same FP sequence
// as the old k_prefix kernel -> bitwise-identical g_c).
__global__ __launch_bounds__(K3_BT) void k_scan(
    const float* __restrict__ x,
    const float* __restrict__ alpha_p, const float* __restrict__ gamma_p,
    const float* __restrict__ inits,   const float* __restrict__ level_p)
{
    __shared__ float sm_ts[TSBUF];
    __shared__ float sm_xn[BSPAN];
    __shared__ float sm_l [BSPAN];
    __shared__ float sm_s [BSPAN];
    __shared__ unsigned s_pos;

    const int tid        = threadIdx.x;
    const int wid        = tid >> 5;
    const int lane       = tid & 31;
    const int blk_t0     = blockIdx.x * BSPAN;
    const int slice_base = blk_t0 - W_UP;

    // stage ts slice: ts[u] = (u < T) ? x[0,u,0] : x[u-T+1, T-1, 0]
    for (int idx = tid; idx < SLICE + 32; idx += K3_BT) {
        int u = slice_base + idx;
        float v = 1.0f;
        if (u >= 0 && u < NTS)
            v = (u < TDIM) ? x[u] : x[(u - (TDIM - 1)) * TDIM + (TDIM - 1)];
        sm_ts[idx] = v;
    }
    __syncthreads();

    const float a  = *alpha_p;
    const float g  = *gamma_p;
    const float ka = 1.0f - a;
    const float kg = 1.0f - g;
    const float ka2 = ka * ka, ka4 = ka2 * ka2, ka8 = ka4 * ka4, ka16 = ka8 * ka8;

    const int chunk = blockIdx.x * WPB + wid;
    const int t0    = chunk * CH_S;
    const int u0    = t0 - W_UP;
    const int base  = wid * CH_S;      // sm_ts index of this warp's u0

    // per-lane constant ka^(lane+1)
    float kaPow = ka;
    for (int i = 0; i < lane; i++) kaPow *= ka;

    // lane j owns slot j: q = inits[(j + t0) % 24]
    float q, iq;
    {
        int idx = (lane + t0) % MQ;
        q  = inits[idx];
        iq = frcp(q);
    }
    float l = *level_p;

    int kk = 0;
    // ---- clamped prefix (chunks with t0 < W_UP): skip whole macros; one
    // partial macro where lanes j < rem use identity affines & skip updates.
    if (u0 < 0) {
        int m   = (-u0) / MQ;
        int rem = (-u0) % MQ;
        kk = m;
        if (rem > 0) {
            int off = base + kk * MQ;
            float y = sm_ts[off + lane];
            float r = y * iq;
            bool act = (lane >= rem);
            float Av = act ? ka      : 1.0f;
            float Bv = act ? a * r   : 0.0f;
#pragma unroll
            for (int s = 1; s < MQ; s <<= 1) {
                float Bp = __shfl_up_sync(0xffffffffu, Bv, s);
                float Ap = __shfl_up_sync(0xffffffffu, Av, s);
                if (lane >= s) { Bv = fmaf(Av, Bp, Bv); Av *= Ap; }
            }
            float ll = fmaf(Av, l, Bv);
            if (act) {
                float il = frcp(ll);
                float sn = fmaf(kg, q, (g * y) * il);
                q  = sn;
                iq = frcp(sn);
            }
            l = __shfl_sync(0xffffffffu, ll, MQ - 1);
            kk++;
        }
    }

    // ---- clean warm loop ----
    for (; kk < WMACRO; kk++) {
        float y = sm_ts[base + kk * MQ + lane];
        float r = y * iq;
        float B = a * r;
        float Bp;
        Bp = __shfl_up_sync(0xffffffffu, B, 1);  if (lane >= 1)  B = fmaf(ka,   Bp, B);
        Bp = __shfl_up_sync(0xffffffffu, B, 2);  if (lane >= 2)  B = fmaf(ka2,  Bp, B);
        Bp = __shfl_up_sync(0xffffffffu, B, 4);  if (lane >= 4)  B = fmaf(ka4,  Bp, B);
        Bp = __shfl_up_sync(0xffffffffu, B, 8);  if (lane >= 8)  B = fmaf(ka8,  Bp, B);
        Bp = __shfl_up_sync(0xffffffffu, B, 16); if (lane >= 16) B = fmaf(ka16, Bp, B);
        float ll = fmaf(kaPow, l, B);
        float il = frcp(ll);
        float sn = fmaf(kg, q, (g * y) * il);
        q  = sn;
        iq = frcp(sn);
        l  = __shfl_sync(0xffffffffu, ll, MQ - 1);
    }

    if (lane == 0) g_lstart[chunk] = l;    // level entering t0

    // ---- output phase: 19 steps (lanes 0..18 produce results) ----
    {
        float y = sm_ts[base + WMACRO * MQ + lane];
        float r = y * iq;
        float B = a * r;
        float Bp;
        Bp = __shfl_up_sync(0xffffffffu, B, 1);  if (lane >= 1)  B = fmaf(ka,   Bp, B);
        Bp = __shfl_up_sync(0xffffffffu, B, 2);  if (lane >= 2)  B = fmaf(ka2,  Bp, B);
        Bp = __shfl_up_sync(0xffffffffu, B, 4);  if (lane >= 4)  B = fmaf(ka4,  Bp, B);
        Bp = __shfl_up_sync(0xffffffffu, B, 8);  if (lane >= 8)  B = fmaf(ka8,  Bp, B);
        Bp = __shfl_up_sync(0xffffffffu, B, 16); if (lane >= 16) B = fmaf(ka16, Bp, B);
        float ll = fmaf(kaPow, l, B);
        float il = frcp(ll);
        float sn = fmaf(kg, q, (g * y) * il);
        if (lane < CH_S) {
            int oo = base + lane;
            sm_xn[oo] = r * il;
            sm_l [oo] = ll;
            sm_s [oo] = sn;
        }
        float le = __shfl_sync(0xffffffffu, ll, CH_S - 1);
        if (lane == 0) g_lend[chunk] = le;   // level entering t0 + 19
    }

    __syncthreads();
    int span = NTS - blk_t0; if (span > BSPAN) span = BSPAN;
    for (int idx = tid; idx < span; idx += K3_BT) {
        int   t = blk_t0 + idx;
        float v = sm_xn[idx];
        g_l[t] = sm_l[idx];
        g_s[t] = sm_s[idx];
        g_xnsh[0][t] = v;                    // xnsh[s][i] = xn[i+s]
        if (t >= 1) g_xnsh[1][t - 1] = v;
        if (t >= 2) g_xnsh[2][t - 2] = v;
        if (t >= 3) g_xnsh[3][t - 3] = v;
    }

    // ---- last-block prefix product (replaces the k_prefix kernel) ----
    __threadfence();
    if (tid == 0) s_pos = atomicAdd(&g_cnt, 1u);
    __syncthreads();
    if (s_pos == K3_NB - 1) {
        float* b0 = sm_ts;          // 1024
        float* b1 = sm_ts + 1024;   // 1024 (TSBUF = 2080 >= 2048)
        for (int k = tid; k < NCHUNK; k += K3_BT) {
            float ratio = 1.0f;
            if (k > 0 && k * CH_S < NTS) ratio = g_lstart[k] / g_lend[k - 1];
            b0[k] = ratio;
        }
        __syncthreads();
        // 10 Hillis-Steele rounds: identical multiply sequence to old k_prefix
        for (int o = 1; o < NCHUNK; o <<= 1) {
            for (int k = tid; k < NCHUNK; k += K3_BT)
                b1[k] = (k >= o) ? b0[k] * b0[k - o] : b0[k];
            __syncthreads();
            float* tmp = b0; b0 = b1; b1 = tmp;
        }
        for (int k = tid; k < NCHUNK; k += K3_BT) g_c[k] = b0[k];
        if (tid == 0) g_cnt = 0;             // deterministic reset for replay
    }
}

// ============ K2: fused x_out + denorm ============
// x_out: 1 aligned LDG.128 (sh-shifted copy; sh warp-uniform) + 1 STG.128
// per 16 output bytes. denorm applies the symmetry correction at read time.
__global__ void k_out(float* __restrict__ out) {
    int bx = blockIdx.x;
    if (bx < XB) {
        int i4   = bx * blockDim.x + threadIdx.x;
        int i    = i4 << 2;
        int b    = i >> 11;
        int t    = i & (TDIM - 1);
        int base = b + t;
        int qq   = base >> 2;
        int sh   = base & 3;
        const float4* p = reinterpret_cast<const float4*>(g_xnsh[sh]);
        reinterpret_cast<float4*>(out)[i4] = p[qq];
    } else {
        int i = (bx - XB) * blockDim.x + threadIdx.x;
        if (i < DEN_N) {
            int b = i / 48;
            int r = i - b * 48;
            int h = r >> 1;
            float v;
            if (r & 1) {
                int t = (TDIM - MQ) + b + h;
                v = g_s[t] * g_c[t / CH_S];          // s_true = s * c
            } else {
                int t = (TDIM - 1) + b;
                v = g_l[t] / g_c[t / CH_S];          // l_true = l / c
            }
            out[XOUT_N + i] = v;
        }
    }
}

extern "C" void kernel_launch(void* const* d_in, const int* in_sizes, int n_in,
                              void* d_out, int out_size) {
    const float* x     = (const float*)d_in[0];
    const float* alpha = (const float*)d_in[1];
    const float* gamma = (const float*)d_in[2];
    const float* inits = (const float*)d_in[3];
    const float* level = (const float*)d_in[4];
    float* out = (float*)d_out;

    k_scan<<<K3_NB, K3_BT>>>(x, alpha, gamma, inits, level);
    int nb = (out_size >= XOUT_N + DEN_N) ? (XB + DB) : XB;
    k_out<<<nb, 256>>>(out);
}

// round 11
// speedup vs baseline: 1.4522x; 1.4522x over previous
#include <cuda_runtime.h>

// ---------------- problem constants ----------------
#define TDIM   2048
#define BDIM   16384
#define NTS    18431            // TDIM + BDIM - 1
#define MQ     24               // seasonality period == HORIZON
#define XOUT_N (BDIM * TDIM)    // 33554432
#define DEN_N  (BDIM * 48)      // 786432

// ---------------- chunk-parallel scan config (R7 layout) ----------------
#define W_UP   1440             // warm-up steps (60 seasonal cycles)
#define WMACRO (W_UP / MQ)      // 60
#define CH_S   19               // output steps per chunk
#define WPB    4                // warps (=chunks) per block
#define K3_BT  (WPB * 32)       // 128 threads
#define K3_NB  243              // 972 chunk slots >= 971 needed
#define NCHUNK 1024             // logical chunk-index space
#define BSPAN  (WPB * CH_S)     // 76 output steps per block
#define SLICE  (W_UP + BSPAN)   // 1516 ts floats used
#define TSBUF  2080             // sm_ts size: >= SLICE+32 pad, >= 2048 for prefix

#define XB     (XOUT_N / 1024)           // 32768 xout blocks (1024 outputs each)
#define DB     ((DEN_N + 255) / 256)     // 3072 denorm blocks

// ---------------- device scratch (no allocs allowed) ----------------
__device__ __align__(16) float g_xn[18448];   // padded: reads up to idx 18434
__device__ float g_l [NTS];
__device__ float g_s [NTS];
__device__ float g_lstart[NCHUNK];
__device__ float g_lend  [NCHUNK];
__device__ float g_c     [NCHUNK];
__device__ unsigned g_cnt;                    // zero-init; reset each launch

__device__ __forceinline__ float frcp(float x) {
    float r;
    asm("rcp.approx.ftz.f32 %0, %1;" : "=f"(r) : "f"(x));
    return r;
}

// ============ K1: lane-per-slot warp-parallel ES scan (R7 numerics) ========
// One warp = one 19-step chunk warm-started 1440 steps back. Lane j owns
// seasonal slot j. Level chain solved per 24-step macro by a Kogge-Stone
// affine scan. LAST block to finish runs the 1024-entry prefix product
// (same FP sequence as the old k_prefix kernel -> bitwise-identical g_c).
__global__ __launch_bounds__(K3_BT) void k_scan(
    const float* __restrict__ x,
    const float* __restrict__ alpha_p, const float* __restrict__ gamma_p,
    const float* __restrict__ inits,   const float* __restrict__ level_p)
{
    __shared__ float sm_ts[TSBUF];
    __shared__ float sm_xn[BSPAN];
    __shared__ float sm_l [BSPAN];
    __shared__ float sm_s [BSPAN];
    __shared__ unsigned s_pos;

    const int tid        = threadIdx.x;
    const int wid        = tid >> 5;
    const int lane       = tid & 31;
    const int blk_t0     = blockIdx.x * BSPAN;
    const int slice_base = blk_t0 - W_UP;

    // stage ts slice: ts[u] = (u < T) ? x[0,u,0] : x[u-T+1, T-1, 0]
    for (int idx = tid; idx < SLICE + 32; idx += K3_BT) {
        int u = slice_base + idx;
        float v = 1.0f;
        if (u >= 0 && u < NTS)
            v = (u < TDIM) ? x[u] : x[(u - (TDIM - 1)) * TDIM + (TDIM - 1)];
        sm_ts[idx] = v;
    }
    __syncthreads();

    const float a  = *alpha_p;
    const float g  = *gamma_p;
    const float ka = 1.0f - a;
    const float kg = 1.0f - g;
    const float ka2 = ka * ka, ka4 = ka2 * ka2, ka8 = ka4 * ka4, ka16 = ka8 * ka8;

    const int chunk = blockIdx.x * WPB + wid;
    const int t0    = chunk * CH_S;
    const int u0    = t0 - W_UP;
    const int base  = wid * CH_S;      // sm_ts index of this warp's u0

    // per-lane constant ka^(lane+1)
    float kaPow = ka;
    for (int i = 0; i < lane; i++) kaPow *= ka;

    // lane j owns slot j: q = inits[(j + t0) % 24]
    float q, iq;
    {
        int idx = (lane + t0) % MQ;
        q  = inits[idx];
        iq = frcp(q);
    }
    float l = *level_p;

    int kk = 0;
    // ---- clamped prefix (chunks with t0 < W_UP): skip whole macros; one
    // partial macro where lanes j < rem use identity affines & skip updates.
    if (u0 < 0) {
        int m   = (-u0) / MQ;
        int rem = (-u0) % MQ;
        kk = m;
        if (rem > 0) {
            int off = base + kk * MQ;
            float y = sm_ts[off + lane];
            float r = y * iq;
            bool act = (lane >= rem);
            float Av = act ? ka      : 1.0f;
            float Bv = act ? a * r   : 0.0f;
#pragma unroll
            for (int s = 1; s < MQ; s <<= 1) {
                float Bp = __shfl_up_sync(0xffffffffu, Bv, s);
                float Ap = __shfl_up_sync(0xffffffffu, Av, s);
                if (lane >= s) { Bv = fmaf(Av, Bp, Bv); Av *= Ap; }
            }
            float ll = fmaf(Av, l, Bv);
            if (act) {
                float il = frcp(ll);
                float sn = fmaf(kg, q, (g * y) * il);
                q  = sn;
                iq = frcp(sn);
            }
            l = __shfl_sync(0xffffffffu, ll, MQ - 1);
            kk++;
        }
    }

    // ---- clean warm loop ----
    for (; kk < WMACRO; kk++) {
        float y = sm_ts[base + kk * MQ + lane];
        float r = y * iq;
        float B = a * r;
        float Bp;
        Bp = __shfl_up_sync(0xffffffffu, B, 1);  if (lane >= 1)  B = fmaf(ka,   Bp, B);
        Bp = __shfl_up_sync(0xffffffffu, B, 2);  if (lane >= 2)  B = fmaf(ka2,  Bp, B);
        Bp = __shfl_up_sync(0xffffffffu, B, 4);  if (lane >= 4)  B = fmaf(ka4,  Bp, B);
        Bp = __shfl_up_sync(0xffffffffu, B, 8);  if (lane >= 8)  B = fmaf(ka8,  Bp, B);
        Bp = __shfl_up_sync(0xffffffffu, B, 16); if (lane >= 16) B = fmaf(ka16, Bp, B);
        float ll = fmaf(kaPow, l, B);
        float il = frcp(ll);
        float sn = fmaf(kg, q, (g * y) * il);
        q  = sn;
        iq = frcp(sn);
        l  = __shfl_sync(0xffffffffu, ll, MQ - 1);
    }

    if (lane == 0) g_lstart[chunk] = l;    // level entering t0

    // ---- output phase: 19 steps (lanes 0..18 produce results) ----
    {
        float y = sm_ts[base + WMACRO * MQ + lane];
        float r = y * iq;
        float B = a * r;
        float Bp;
        Bp = __shfl_up_sync(0xffffffffu, B, 1);  if (lane >= 1)  B = fmaf(ka,   Bp, B);
        Bp = __shfl_up_sync(0xffffffffu, B, 2);  if (lane >= 2)  B = fmaf(ka2,  Bp, B);
        Bp = __shfl_up_sync(0xffffffffu, B, 4);  if (lane >= 4)  B = fmaf(ka4,  Bp, B);
        Bp = __shfl_up_sync(0xffffffffu, B, 8);  if (lane >= 8)  B = fmaf(ka8,  Bp, B);
        Bp = __shfl_up_sync(0xffffffffu, B, 16); if (lane >= 16) B = fmaf(ka16, Bp, B);
        float ll = fmaf(kaPow, l, B);
        float il = frcp(ll);
        float sn = fmaf(kg, q, (g * y) * il);
        if (lane < CH_S) {
            int oo = base + lane;
            sm_xn[oo] = r * il;
            sm_l [oo] = ll;
            sm_s [oo] = sn;
        }
        float le = __shfl_sync(0xffffffffu, ll, CH_S - 1);
        if (lane == 0) g_lend[chunk] = le;   // level entering t0 + 19
    }

    __syncthreads();
    int span = NTS - blk_t0; if (span > BSPAN) span = BSPAN;
    for (int idx = tid; idx < span; idx += K3_BT) {
        int t = blk_t0 + idx;
        g_xn[t] = sm_xn[idx];
        g_l [t] = sm_l [idx];
        g_s [t] = sm_s [idx];
    }

    // ---- last-block prefix product (replaces the k_prefix kernel) ----
    __threadfence();
    if (tid == 0) s_pos = atomicAdd(&g_cnt, 1u);
    __syncthreads();
    if (s_pos == K3_NB - 1) {
        float* b0 = sm_ts;          // 1024
        float* b1 = sm_ts + 1024;   // 1024 (TSBUF = 2080 >= 2048)
        for (int k = tid; k < NCHUNK; k += K3_BT) {
            float ratio = 1.0f;
            if (k > 0 && k * CH_S < NTS) ratio = g_lstart[k] / g_lend[k - 1];
            b0[k] = ratio;
        }
        __syncthreads();
        // 10 Hillis-Steele rounds: identical multiply sequence to old k_prefix
        for (int o = 1; o < NCHUNK; o <<= 1) {
            for (int k = tid; k < NCHUNK; k += K3_BT)
                b1[k] = (k >= o) ? b0[k] * b0[k - o] : b0[k];
            __syncthreads();
            float* tmp = b0; b0 = b1; b1 = tmp;
        }
        for (int k = tid; k < NCHUNK; k += K3_BT) g_c[k] = b0[k];
        if (tid == 0) g_cnt = 0;             // deterministic reset for replay
    }
}

// ============ K2: fused x_out + denorm, smem-staged ============
// x_out block = 1024 consecutive outputs in one row (b = bx>>1 uniform).
// Stage the 1028 xn floats it needs into smem (coalesced, L2-resident 74KB
// working set), then 1 aligned LDS.128 + 1 streaming STG.128 per thread.
__global__ __launch_bounds__(256) void k_out(float* __restrict__ out) {
    __shared__ __align__(16) float sm[1028];
    int bx  = blockIdx.x;
    int tid = threadIdx.x;
    if (bx < XB) {
        int b     = bx >> 1;              // row (uniform in block)
        int t0    = (bx & 1) << 10;       // 0 or 1024
        int base0 = b + t0;               // xn index of output 0
        for (int k = tid; k < 1028; k += 256)
            sm[k] = g_xn[base0 + k];      // max idx 18434 < 18448 pad
        __syncthreads();
        float4 v = *reinterpret_cast<const float4*>(&sm[tid << 2]);
        __stcs(reinterpret_cast<float4*>(out) + (bx << 8) + tid, v);
    } else {
        int i = (bx - XB) * 256 + tid;
        if (i < DEN_N) {
            int b = i / 48;
            int r = i - b * 48;
            int h = r >> 1;
            float v;
            if (r & 1) {
                int t = (TDIM - MQ) + b + h;
                v = g_s[t] * g_c[t / CH_S];          // s_true = s * c
            } else {
                int t = (TDIM - 1) + b;
                v = g_l[t] / g_c[t / CH_S];          // l_true = l / c
            }
            out[XOUT_N + i] = v;
        }
    }
}

extern "C" void kernel_launch(void* const* d_in, const int* in_sizes, int n_in,
                              void* d_out, int out_size) {
    const float* x     = (const float*)d_in[0];
    const float* alpha = (const float*)d_in[1];
    const float* gamma = (const float*)d_in[2];
    const float* inits = (const float*)d_in[3];
    const float* level = (const float*)d_in[4];
    float* out = (float*)d_out;

    k_scan<<<K3_NB, K3_BT>>>(x, alpha, gamma, inits, level);
    int nb = (out_size >= XOUT_N + DEN_N) ? (XB + DB) : XB;
    k_out<<<nb, 256>>>(out);
}

// round 12
// speedup vs baseline: 1.5899x; 1.0948x over previous
#include <cuda_runtime.h>

// ---------------- problem constants ----------------
#define TDIM   2048
#define BDIM   16384
#define NTS    18431            // TDIM + BDIM - 1
#define MQ     24               // seasonality period == HORIZON
#define XOUT_N (BDIM * TDIM)    // 33554432
#define DEN_N  (BDIM * 48)      // 786432

// ---------------- chunk-parallel scan config (R7 layout) ----------------
#define W_UP   1440             // warm-up steps (60 seasonal cycles)
#define WMACRO (W_UP / MQ)      // 60
#define CH_S   19               // output steps per chunk
#define WPB    4                // warps (=chunks) per block
#define K3_BT  (WPB * 32)       // 128 threads
#define K3_NB  243              // 972 chunk slots >= 971 needed
#define NCHUNK 1024             // logical chunk-index space
#define BSPAN  (WPB * CH_S)     // 76 output steps per block
#define SLICE  (W_UP + BSPAN)   // 1516 ts floats used
#define TSBUF  2080             // sm_ts size: >= SLICE+32 pad, >= 2048 for prefix

// ---------------- k_out tiling ----------------
#define ROWS_PB 16                       // rows per xout block
#define XB4     (BDIM / ROWS_PB)         // 1024 xout blocks
#define DB      ((DEN_N + 255) / 256)    // 3072 denorm blocks
#define STAGE   2080                     // smem floats staged (>= 16+2050, /4)

// ---------------- device scratch (no allocs allowed) ----------------
__device__ __align__(16) float g_xn[18448];   // padded: reads up to idx 18447
__device__ float g_l [NTS];
__device__ float g_s [NTS];
__device__ float g_lstart[NCHUNK];
__device__ float g_lend  [NCHUNK];
__device__ float g_c     [NCHUNK];
__device__ unsigned g_cnt;                    // zero-init; reset each launch

__device__ __forceinline__ float frcp(float x) {
    float r;
    asm("rcp.approx.ftz.f32 %0, %1;" : "=f"(r) : "f"(x));
    return r;
}

// ============ K1: lane-per-slot warp-parallel ES scan (R7 numerics) ========
// One warp = one 19-step chunk warm-started 1440 steps back. Lane j owns
// seasonal slot j. Level chain solved per 24-step macro by a Kogge-Stone
// affine scan. LAST block to finish runs the 1024-entry prefix product
// (same FP sequence as the old k_prefix kernel -> bitwise-identical g_c).
__global__ __launch_bounds__(K3_BT) void k_scan(
    const float* __restrict__ x,
    const float* __restrict__ alpha_p, const float* __restrict__ gamma_p,
    const float* __restrict__ inits,   const float* __restrict__ level_p)
{
    __shared__ float sm_ts[TSBUF];
    __shared__ float sm_xn[BSPAN];
    __shared__ float sm_l [BSPAN];
    __shared__ float sm_s [BSPAN];
    __shared__ unsigned s_pos;

    const int tid        = threadIdx.x;
    const int wid        = tid >> 5;
    const int lane       = tid & 31;
    const int blk_t0     = blockIdx.x * BSPAN;
    const int slice_base = blk_t0 - W_UP;

    // stage ts slice: ts[u] = (u < T) ? x[0,u,0] : x[u-T+1, T-1, 0]
    for (int idx = tid; idx < SLICE + 32; idx += K3_BT) {
        int u = slice_base + idx;
        float v = 1.0f;
        if (u >= 0 && u < NTS)
            v = (u < TDIM) ? x[u] : x[(u - (TDIM - 1)) * TDIM + (TDIM - 1)];
        sm_ts[idx] = v;
    }
    __syncthreads();

    const float a  = *alpha_p;
    const float g  = *gamma_p;
    const float ka = 1.0f - a;
    const float kg = 1.0f - g;
    const float ka2 = ka * ka, ka4 = ka2 * ka2, ka8 = ka4 * ka4, ka16 = ka8 * ka8;

    const int chunk = blockIdx.x * WPB + wid;
    const int t0    = chunk * CH_S;
    const int u0    = t0 - W_UP;
    const int base  = wid * CH_S;      // sm_ts index of this warp's u0

    // per-lane constant ka^(lane+1)
    float kaPow = ka;
    for (int i = 0; i < lane; i++) kaPow *= ka;

    // lane j owns slot j: q = inits[(j + t0) % 24]
    float q, iq;
    {
        int idx = (lane + t0) % MQ;
        q  = inits[idx];
        iq = frcp(q);
    }
    float l = *level_p;

    int kk = 0;
    // ---- clamped prefix (chunks with t0 < W_UP): skip whole macros; one
    // partial macro where lanes j < rem use identity affines & skip updates.
    if (u0 < 0) {
        int m   = (-u0) / MQ;
        int rem = (-u0) % MQ;
        kk = m;
        if (rem > 0) {
            int off = base + kk * MQ;
            float y = sm_ts[off + lane];
            float r = y * iq;
            bool act = (lane >= rem);
            float Av = act ? ka      : 1.0f;
            float Bv = act ? a * r   : 0.0f;
#pragma unroll
            for (int s = 1; s < MQ; s <<= 1) {
                float Bp = __shfl_up_sync(0xffffffffu, Bv, s);
                float Ap = __shfl_up_sync(0xffffffffu, Av, s);
                if (lane >= s) { Bv = fmaf(Av, Bp, Bv); Av *= Ap; }
            }
            float ll = fmaf(Av, l, Bv);
            if (act) {
                float il = frcp(ll);
                float sn = fmaf(kg, q, (g * y) * il);
                q  = sn;
                iq = frcp(sn);
            }
            l = __shfl_sync(0xffffffffu, ll, MQ - 1);
            kk++;
        }
    }

    // ---- clean warm loop ----
    for (; kk < WMACRO; kk++) {
        float y = sm_ts[base + kk * MQ + lane];
        float r = y * iq;
        float B = a * r;
        float Bp;
        Bp = __shfl_up_sync(0xffffffffu, B, 1);  if (lane >= 1)  B = fmaf(ka,   Bp, B);
        Bp = __shfl_up_sync(0xffffffffu, B, 2);  if (lane >= 2)  B = fmaf(ka2,  Bp, B);
        Bp = __shfl_up_sync(0xffffffffu, B, 4);  if (lane >= 4)  B = fmaf(ka4,  Bp, B);
        Bp = __shfl_up_sync(0xffffffffu, B, 8);  if (lane >= 8)  B = fmaf(ka8,  Bp, B);
        Bp = __shfl_up_sync(0xffffffffu, B, 16); if (lane >= 16) B = fmaf(ka16, Bp, B);
        float ll = fmaf(kaPow, l, B);
        float il = frcp(ll);
        float sn = fmaf(kg, q, (g * y) * il);
        q  = sn;
        iq = frcp(sn);
        l  = __shfl_sync(0xffffffffu, ll, MQ - 1);
    }

    if (lane == 0) g_lstart[chunk] = l;    // level entering t0

    // ---- output phase: 19 steps (lanes 0..18 produce results) ----
    {
        float y = sm_ts[base + WMACRO * MQ + lane];
        float r = y * iq;
        float B = a * r;
        float Bp;
        Bp = __shfl_up_sync(0xffffffffu, B, 1);  if (lane >= 1)  B = fmaf(ka,   Bp, B);
        Bp = __shfl_up_sync(0xffffffffu, B, 2);  if (lane >= 2)  B = fmaf(ka2,  Bp, B);
        Bp = __shfl_up_sync(0xffffffffu, B, 4);  if (lane >= 4)  B = fmaf(ka4,  Bp, B);
        Bp = __shfl_up_sync(0xffffffffu, B, 8);  if (lane >= 8)  B = fmaf(ka8,  Bp, B);
        Bp = __shfl_up_sync(0xffffffffu, B, 16); if (lane >= 16) B = fmaf(ka16, Bp, B);
        float ll = fmaf(kaPow, l, B);
        float il = frcp(ll);
        float sn = fmaf(kg, q, (g * y) * il);
        if (lane < CH_S) {
            int oo = base + lane;
            sm_xn[oo] = r * il;
            sm_l [oo] = ll;
            sm_s [oo] = sn;
        }
        float le = __shfl_sync(0xffffffffu, ll, CH_S - 1);
        if (lane == 0) g_lend[chunk] = le;   // level entering t0 + 19
    }

    __syncthreads();
    int span = NTS - blk_t0; if (span > BSPAN) span = BSPAN;
    for (int idx = tid; idx < span; idx += K3_BT) {
        int t = blk_t0 + idx;
        g_xn[t] = sm_xn[idx];
        g_l [t] = sm_l [idx];
        g_s [t] = sm_s [idx];
    }

    // ---- last-block prefix product (replaces the k_prefix kernel) ----
    __threadfence();
    if (tid == 0) s_pos = atomicAdd(&g_cnt, 1u);
    __syncthreads();
    if (s_pos == K3_NB - 1) {
        float* b0 = sm_ts;          // 1024
        float* b1 = sm_ts + 1024;   // 1024 (TSBUF = 2080 >= 2048)
        for (int k = tid; k < NCHUNK; k += K3_BT) {
            float ratio = 1.0f;
            if (k > 0 && k * CH_S < NTS) ratio = g_lstart[k] / g_lend[k - 1];
            b0[k] = ratio;
        }
        __syncthreads();
        // 10 Hillis-Steele rounds: identical multiply sequence to old k_prefix
        for (int o = 1; o < NCHUNK; o <<= 1) {
            for (int k = tid; k < NCHUNK; k += K3_BT)
                b1[k] = (k >= o) ? b0[k] * b0[k - o] : b0[k];
            __syncthreads();
            float* tmp = b0; b0 = b1; b1 = tmp;
        }
        for (int k = tid; k < NCHUNK; k += K3_BT) g_c[k] = b0[k];
        if (tid == 0) g_cnt = 0;             // deterministic reset for replay
    }
}

// ============ K2: fused x_out + denorm, row-tiled smem stage ============
// xout block = 16 complete rows (32768 outputs). All xn values those rows
// need are just xn[r0 .. r0+2065] (8.3 KB) -- stage once, then every output
// float4 is 1-2 aligned LDS.128 + warp-uniform mux + 1 streaming STG.128.
// L2 read traffic: 1024 * 8.3 KB = 8.5 MB (vs 134 MB unstaged).
__global__ __launch_bounds__(256) void k_out(float* __restrict__ out) {
    __shared__ __align__(16) float sm[STAGE];
    int bx  = blockIdx.x;
    int tid = threadIdx.x;
    if (bx < XB4) {
        int r0 = bx << 4;                             // first row of the tile
        for (int k = tid; k < STAGE; k += 256)
            sm[k] = g_xn[r0 + k];                     // max 16368+2079 < 18448
        __syncthreads();
        const float4* sm4 = reinterpret_cast<const float4*>(sm);
        float4* o4 = reinterpret_cast<float4*>(out) + (bx << 13);
#pragma unroll 4
        for (int it = 0; it < 32; it++) {
            int j   = it * 256 + tid;                 // float4 index in tile
            int rel = (j >> 9) + ((j & 511) << 2);    // (b-r0) + t
            int q0  = rel >> 2;
            int sh  = rel & 3;                        // == (j>>9)&3, warp-uniform
            float4 f0 = sm4[q0];
            float4 v;
            if (sh == 0) {
                v = f0;
            } else {
                float4 f1 = sm4[q0 + 1];
                if (sh == 1)      v = make_float4(f0.y, f0.z, f0.w, f1.x);
                else if (sh == 2) v = make_float4(f0.z, f0.w, f1.x, f1.y);
                else              v = make_float4(f0.w, f1.x, f1.y, f1.z);
            }
            __stcs(o4 + j, v);
        }
    } else {
        int i = (bx - XB4) * 256 + tid;
        if (i < DEN_N) {
            int b = i / 48;
            int r = i - b * 48;
            int h = r >> 1;
            float v;
            if (r & 1) {
                int t = (TDIM - MQ) + b + h;
                v = g_s[t] * g_c[t / CH_S];          // s_true = s * c
            } else {
                int t = (TDIM - 1) + b;
                v = g_l[t] / g_c[t / CH_S];          // l_true = l / c
            }
            out[XOUT_N + i] = v;
        }
    }
}

extern "C" void kernel_launch(void* const* d_in, const int* in_sizes, int n_in,
                              void* d_out, int out_size) {
    const float* x     = (const float*)d_in[0];
    const float* alpha = (const float*)d_in[1];
    const float* gamma = (const float*)d_in[2];
    const float* inits = (const float*)d_in[3];
    const float* level = (const float*)d_in[4];
    float* out = (float*)d_out;

    k_scan<<<K3_NB, K3_BT>>>(x, alpha, gamma, inits, level);
    int nb = (out_size >= XOUT_N + DEN_N) ? (XB4 + DB) : XB4;
    k_out<<<nb, 256>>>(out);
}